// round 4
// baseline (speedup 1.0000x reference)
#include <cuda_runtime.h>

#define CHANNELS  8
#define IN_CH     8
#define NPARAMS   169      // 80 + 64 + 8 + 8 + 8 + 1
#define H_        128
#define W_        192
#define HW_       (H_ * W_)
#define TILE_R    32       // output logit rows per block
#define MAX_INST  128

typedef unsigned long long u64;

// ---- packed fp32x2 helpers (Blackwell) -------------------------------------
__device__ __forceinline__ u64 fma2(u64 a, u64 b, u64 c) {
    u64 d;
    asm("fma.rn.f32x2 %0, %1, %2, %3;" : "=l"(d) : "l"(a), "l"(b), "l"(c));
    return d;
}
__device__ __forceinline__ u64 pack2(float lo, float hi) {
    u64 d;
    asm("mov.b64 %0, {%1, %2};" : "=l"(d) : "f"(lo), "f"(hi));
    return d;
}
__device__ __forceinline__ void unpack2(u64 v, float& lo, float& hi) {
    asm("mov.b64 {%0, %1}, %2;" : "=f"(lo), "=f"(hi) : "l"(v));
}
__device__ __forceinline__ u64 relu2(u64 v) {
    float lo, hi;
    unpack2(v, lo, hi);
    return pack2(fmaxf(lo, 0.0f), fmaxf(hi, 0.0f));
}

// ---------------------------------------------------------------------------
// Fused kernel. One block = (one instance) x (32-row tile).
// Phase 1: MLP for 33 logit rows (1 halo row above, clamped) into shared mem.
//          Units of 8 consecutive pixels per thread-iteration (4x f32x2).
// Phase 2: aligned 2x bilinear upsample straight from shared mem to gmem.
//   O[2r,  2c  ] = 0.25*(L[r-1,c-1] + L[r-1,c] + L[r,c-1] + L[r,c])
//   O[2r,  2c+1] = 0.5 *(L[r-1,c]   + L[r,c])
//   O[2r+1,2c  ] = 0.5 *(L[r,c-1]   + L[r,c])
//   O[2r+1,2c+1] =       L[r,c]          (r-1, c-1 clamped at 0)
// ---------------------------------------------------------------------------
__global__ __launch_bounds__(256)
void fused_mask_kernel(const float* __restrict__ mask_feats,   // (N, 8, H, W)
                       const float* __restrict__ params,       // (n_inst, 169)
                       const float* __restrict__ inst_loc,     // (n_inst, 2)
                       const float* __restrict__ soi_tab,      // (6,)
                       const int*   __restrict__ im_inds,      // (n_inst,)
                       const int*   __restrict__ fpn_levels,   // (n_inst,)
                       float*       __restrict__ out)
{
    __shared__ __align__(16) float2 sp2[NPARAMS];           // duplicated weights
    __shared__ __align__(16) float  st[(TILE_R + 1) * W_];  // logit tile + halo
    __shared__ float s_ix, s_iy, s_isoi;
    __shared__ int   s_im;

    const int n   = blockIdx.y;                 // instance
    const int r0  = blockIdx.x * TILE_R;        // first output logit row
    const int tid = threadIdx.x;

    for (int i = tid; i < NPARAMS; i += 256) {
        float v = params[(size_t)n * NPARAMS + i];
        sp2[i] = make_float2(v, v);
    }
    if (tid == 0) {
        s_ix   = inst_loc[2 * n + 0];
        s_iy   = inst_loc[2 * n + 1];
        s_isoi = 1.0f / soi_tab[fpn_levels[n]];
        s_im   = im_inds[n];
    }
    __syncthreads();

    const u64*  prm = reinterpret_cast<const u64*>(sp2);
    const float ix = s_ix, iy = s_iy, s = s_isoi;
    const float* featbase = mask_feats + (size_t)s_im * IN_CH * HW_;

    // ---------------- Phase 1: MLP into shared tile -------------------------
    // units: (TILE_R+1) rows x 24 strips of 8 px = 792
    #pragma unroll 1
    for (int u = tid; u < (TILE_R + 1) * (W_ / 8); u += 256) {
        const int row  = u / (W_ / 8);
        const int col8 = (u % (W_ / 8)) * 8;
        const int gr   = max(r0 + row - 1, 0);

        const float dx  = ix - ((float)col8 * 8.0f + 4.0f);
        const float ryv = (iy - ((float)gr * 8.0f + 4.0f)) * s;
        u64 rx[4];
        #pragma unroll
        for (int pp = 0; pp < 4; pp++)
            rx[pp] = pack2((dx - (float)(16 * pp)) * s,
                           (dx - (float)(16 * pp + 8)) * s);
        const u64 ry = pack2(ryv, ryv);

        const float4* f4 = reinterpret_cast<const float4*>(
            featbase + (size_t)gr * W_ + col8);

        // layer 0: bias + location terms
        u64 h[CHANNELS][4];
        #pragma unroll
        for (int o = 0; o < CHANNELS; o++) {
            u64 b   = prm[152 + o];
            u64 wx  = prm[o * 10 + 0];
            u64 wy  = prm[o * 10 + 1];
            u64 byy = fma2(wy, ry, b);
            #pragma unroll
            for (int pp = 0; pp < 4; pp++)
                h[o][pp] = fma2(wx, rx[pp], byy);
        }
        // layer 0: feature channels
        #pragma unroll
        for (int c = 0; c < IN_CH; c++) {
            float4 v0 = f4[c * (HW_ / 4)];
            float4 v1 = f4[c * (HW_ / 4) + 1];
            u64 fp[4] = { pack2(v0.x, v0.y), pack2(v0.z, v0.w),
                          pack2(v1.x, v1.y), pack2(v1.z, v1.w) };
            #pragma unroll
            for (int o = 0; o < CHANNELS; o++) {
                u64 w = prm[o * 10 + 2 + c];
                #pragma unroll
                for (int pp = 0; pp < 4; pp++)
                    h[o][pp] = fma2(w, fp[pp], h[o][pp]);
            }
        }
        #pragma unroll
        for (int o = 0; o < CHANNELS; o++)
            #pragma unroll
            for (int pp = 0; pp < 4; pp++)
                h[o][pp] = relu2(h[o][pp]);

        // layer 1 with layer 2 fused
        u64 acc[4];
        {
            u64 b2 = prm[168];
            #pragma unroll
            for (int pp = 0; pp < 4; pp++) acc[pp] = b2;
        }
        #pragma unroll
        for (int o = 0; o < CHANNELS; o++) {
            u64 b1 = prm[160 + o];
            u64 q[4];
            #pragma unroll
            for (int pp = 0; pp < 4; pp++) q[pp] = b1;
            #pragma unroll
            for (int c = 0; c < CHANNELS; c++) {
                u64 w = prm[80 + o * 8 + c];
                #pragma unroll
                for (int pp = 0; pp < 4; pp++)
                    q[pp] = fma2(w, h[c][pp], q[pp]);
            }
            u64 w2 = prm[144 + o];
            #pragma unroll
            for (int pp = 0; pp < 4; pp++)
                acc[pp] = fma2(w2, relu2(q[pp]), acc[pp]);
        }

        float o0, o1, o2, o3, o4, o5, o6, o7;
        unpack2(acc[0], o0, o1);  unpack2(acc[1], o2, o3);
        unpack2(acc[2], o4, o5);  unpack2(acc[3], o6, o7);
        float4* dst = reinterpret_cast<float4*>(st + row * W_ + col8);
        dst[0] = make_float4(o0, o1, o2, o3);
        dst[1] = make_float4(o4, o5, o6, o7);
    }

    __syncthreads();

    // ---------------- Phase 2: upsample from shared tile --------------------
    // units: TILE_R rows x 48 strips of 4 input px = 1536 (= 6 per thread)
    #pragma unroll 1
    for (int u = tid; u < TILE_R * (W_ / 4); u += 256) {
        const int lr = u / (W_ / 4);          // local output row
        const int c0 = (u % (W_ / 4)) * 4;
        const int r  = r0 + lr;               // global logit row

        const float* top = st + lr * W_;        // L[r-1] (halo-shifted)
        const float* bot = st + (lr + 1) * W_;  // L[r]

        const float4 A = *reinterpret_cast<const float4*>(top + c0);
        const float4 B = *reinterpret_cast<const float4*>(bot + c0);
        const float aL = (c0 == 0) ? A.x : top[c0 - 1];
        const float bL = (c0 == 0) ? B.x : bot[c0 - 1];

        const float sL = aL + bL;
        const float s0 = A.x + B.x;
        const float s1 = A.y + B.y;
        const float s2 = A.z + B.z;
        const float s3 = A.w + B.w;

        float4 r0a, r0b, r1a, r1b;
        r0a.x = 0.25f * (sL + s0);  r0a.y = 0.5f * s0;
        r0a.z = 0.25f * (s0 + s1);  r0a.w = 0.5f * s1;
        r0b.x = 0.25f * (s1 + s2);  r0b.y = 0.5f * s2;
        r0b.z = 0.25f * (s2 + s3);  r0b.w = 0.5f * s3;

        r1a.x = 0.5f * (bL + B.x);  r1a.y = B.x;
        r1a.z = 0.5f * (B.x + B.y); r1a.w = B.y;
        r1b.x = 0.5f * (B.y + B.z); r1b.y = B.z;
        r1b.z = 0.5f * (B.z + B.w); r1b.w = B.w;

        float* o = out + (size_t)n * (4 * HW_) + (size_t)(2 * r) * (2 * W_) + 2 * c0;
        reinterpret_cast<float4*>(o)[0]          = r0a;
        reinterpret_cast<float4*>(o)[1]          = r0b;
        reinterpret_cast<float4*>(o + 2 * W_)[0] = r1a;
        reinterpret_cast<float4*>(o + 2 * W_)[1] = r1b;
    }
}

// ---------------------------------------------------------------------------
extern "C" void kernel_launch(void* const* d_in, const int* in_sizes, int n_in,
                              void* d_out, int out_size)
{
    const float* mask_feats = (const float*)d_in[0];
    const float* params     = (const float*)d_in[1];
    const float* inst_loc   = (const float*)d_in[2];
    const float* soi_tab    = (const float*)d_in[3];
    const int*   im_inds    = (const int*)d_in[4];
    const int*   fpn_levels = (const int*)d_in[5];
    float*       out        = (float*)d_out;

    const int n_inst = in_sizes[1] / NPARAMS;   // 128

    dim3 grid(H_ / TILE_R, n_inst);             // 4 x 128 = 512 blocks
    fused_mask_kernel<<<grid, 256>>>(mask_feats, params, inst_loc, soi_tab,
                                     im_inds, fpn_levels, out);
}